// round 11
// baseline (speedup 1.0000x reference)
#include <cuda_runtime.h>
#include <cstdint>

// Problem constants
#define BATCH 64
#define SEQT  512
#define IN    512
#define HID   1024
#define G4    4096
#define KTOT  1536
#define OUTD  512

#define NBLK  128           // persistent grid, 1 CTA/SM
#define NTHR  512           // 16 warps
#define K8TOT 192           // k8: x 0..63, h 64..191
#define K8X   64
#define HSL   16            // h k8 per warp in loop (128/8)

// smem: W fragment-packed (resident) + 8 merged partial tiles
#define WF_FLOATS (K8TOT * 32 * 8)         // 49152 floats = 196608 B
#define P_PITCH   33
#define P_TILE    (32 * P_PITCH)
#define SMEM_TOTAL ((WF_FLOATS + 8 * P_TILE) * 4)   // 230400 B

// ---- device-global scratch ----
__device__ float    d_W[(size_t)G4 * KTOT];              // tf32-rounded, packed cols
__device__ float    d_bias[G4];
__device__ float    d_xfrag[(size_t)SEQT * K8X * 4 * 32 * 4]; // x in fragment order
__device__ float    d_gx[(size_t)SEQT * NBLK * BATCH * 32];   // x-gate proj, per-(t,blk) 8KB
__device__ float    d_hfrag[2 * 128 * 4 * 32 * 4];       // h fragments, dbl-buf
__device__ float    d_hfin[BATCH * HID];
__device__ unsigned d_bar_grp[8 * 64];
__device__ unsigned d_bar_root;

// ============================ helpers =======================================
__device__ __forceinline__ float tf32r(float v) {
    uint32_t r;
    asm("cvt.rna.tf32.f32 %0, %1;" : "=r"(r) : "f"(v));
    return __uint_as_float(r);
}
__device__ __forceinline__ void mma_tf32(float c[4], const uint32_t a[4],
                                         const uint32_t b[2]) {
    asm volatile(
        "mma.sync.aligned.m16n8k8.row.col.f32.tf32.tf32.f32 "
        "{%0,%1,%2,%3}, {%4,%5,%6,%7}, {%8,%9}, {%0,%1,%2,%3};"
        : "+f"(c[0]), "+f"(c[1]), "+f"(c[2]), "+f"(c[3])
        : "r"(a[0]), "r"(a[1]), "r"(a[2]), "r"(a[3]), "r"(b[0]), "r"(b[1]));
}
__device__ __forceinline__ float sigf(float v)     { return 1.f / (1.f + __expf(-v)); }
__device__ __forceinline__ float tanhfast(float v) { return 2.f / (1.f + __expf(-2.f * v)) - 1.f; }

// ============================ prep kernel ===================================
__global__ void prep_kernel(
    const float* __restrict__ x,
    const float* __restrict__ Wxf, const float* __restrict__ Whf, const float* __restrict__ bhf,
    const float* __restrict__ Wxi, const float* __restrict__ Whi, const float* __restrict__ bhi,
    const float* __restrict__ Wxc, const float* __restrict__ Whc, const float* __restrict__ bhc,
    const float* __restrict__ Wxo, const float* __restrict__ Who, const float* __restrict__ bho)
{
    const float* Wx[4] = {Wxf, Wxi, Wxc, Wxo};
    const float* Wh[4] = {Whf, Whi, Whc, Who};
    const float* bh[4] = {bhf, bhi, bhc, bho};

    size_t gid = (size_t)blockIdx.x * blockDim.x + threadIdx.x;
    size_t str = (size_t)gridDim.x * blockDim.x;

    for (size_t i = gid; i < (size_t)G4 * KTOT; i += str) {
        int j = (int)(i / KTOT), k = (int)(i % KTOT);
        int g = (j >> 3) & 3;
        int r = (j >> 5) * 8 + (j & 7);
        float v = (k < IN) ? Wx[g][(size_t)r * IN + k]
                           : Wh[g][(size_t)r * HID + (k - IN)];
        d_W[i] = tf32r(v);
    }
    for (size_t i = gid; i < (size_t)G4; i += str) {
        int g = (int)((i >> 3) & 3);
        int r = (int)((i >> 5) * 8 + (i & 7));
        d_bias[i] = bh[g][r];
    }
    for (size_t i = gid; i < (size_t)SEQT * K8X * 4 * 32 * 4; i += str) {
        int r    = (int)(i & 3);
        int lane = (int)((i >> 2) & 31);
        int mt   = (int)((i >> 7) & 3);
        int k8   = (int)((i >> 9) & 63);
        int t    = (int)(i >> 15);
        int b = mt * 16 + (lane >> 2) + 8 * (r & 1);
        int k = k8 * 8 + (lane & 3) + 4 * (r >> 1);
        d_xfrag[i] = tf32r(x[((size_t)b * SEQT + t) * IN + k]);
    }
    for (size_t i = gid; i < (size_t)2 * 128 * 4 * 32 * 4; i += str)
        d_hfrag[i] = 0.f;
    for (size_t i = gid; i < 8 * 64; i += str) d_bar_grp[i] = 0u;
    if (gid == 0) d_bar_root = 0u;
}

// ============================ fragment loads ================================
__device__ __forceinline__ uint4 ldX(int t, int k8, int mt, int lane)
{
    size_t off = ((((size_t)t * K8X + k8) * 4 + mt) * 32 + lane) * 4;
    return __ldg((const uint4*)&d_xfrag[off]);
}
__device__ __forceinline__ uint4 ldH(int rbuf, int k8h, int mt, int lane)
{
    size_t off = (((size_t)(rbuf * 128 + k8h) * 4 + mt) * 32 + lane) * 4;
    return __ldcg((const uint4*)&d_hfrag[off]);
}
// B fragments for one k8: 2 x LDS.128 from fragment-packed Wf
__device__ __forceinline__ void ldB(const float* Wf, int k8, int lane, uint32_t bfr[4][2])
{
    const float4* p = (const float4*)&Wf[(size_t)(k8 * 32 + lane) * 8];
    float4 w0 = p[0], w1 = p[1];
    bfr[0][0] = __float_as_uint(w0.x); bfr[0][1] = __float_as_uint(w0.y);
    bfr[1][0] = __float_as_uint(w0.z); bfr[1][1] = __float_as_uint(w0.w);
    bfr[2][0] = __float_as_uint(w1.x); bfr[2][1] = __float_as_uint(w1.y);
    bfr[3][0] = __float_as_uint(w1.z); bfr[3][1] = __float_as_uint(w1.w);
}

// ============================ main persistent kernel ========================
__global__ void __launch_bounds__(NTHR, 1) lstm_kernel(
    const float* __restrict__ Wout,
    const float* __restrict__ bout,
    float* __restrict__ out)
{
    extern __shared__ float smf[];
    float* Wf = smf;                 // fragment-packed weights (x + h regions)
    float* P  = smf + WF_FLOATS;     // 8 merged partial tiles

    const int tid  = threadIdx.x;
    const int wid  = tid >> 5;
    const int lane = tid & 31;
    const int g8   = lane >> 2;
    const int ql   = lane & 3;
    const int blk  = blockIdx.x;

    // ---- one-time: pack W columns into LDS.128-friendly fragment order ----
    // Wf[(k8*32+lane)*8 + nt*2 + s] = W[blk*32+nt*8+(lane>>2)][k8*8+(lane&3)+4s]
    for (int j = tid; j < K8TOT * 32; j += NTHR) {
        int k8 = j >> 5, ln = j & 31;
        int g8l = ln >> 2, qll = ln & 3;
#pragma unroll
        for (int nt = 0; nt < 4; nt++) {
            size_t col = (size_t)(blk * 32 + nt * 8 + g8l);
            Wf[(size_t)j * 8 + nt * 2 + 0] = __ldg(&d_W[col * KTOT + k8 * 8 + qll]);
            Wf[(size_t)j * 8 + nt * 2 + 1] = __ldg(&d_W[col * KTOT + k8 * 8 + qll + 4]);
        }
    }
    __syncthreads();

    // ================= PRE-PHASE: gx = x @ Wx^T for all t ==================
    // warp = (tchunk = wid>>1, mhalf = wid&1); t = tchunk + 8*i; M=32, N=32,
    // K=512 per (warp,t). No barriers, fully parallel.
    {
        const int tchunk = wid >> 1;
        const int mbase  = (wid & 1) * 2;
        for (int t = tchunk; t < SEQT; t += 8) {
            float acc[2][4][4];
#pragma unroll
            for (int m2 = 0; m2 < 2; m2++)
#pragma unroll
                for (int nt = 0; nt < 4; nt++)
#pragma unroll
                    for (int c = 0; c < 4; c++) acc[m2][nt][c] = 0.f;

            uint4 apf[2][2];
#pragma unroll
            for (int d = 0; d < 2; d++)
#pragma unroll
                for (int m2 = 0; m2 < 2; m2++)
                    apf[d][m2] = ldX(t, d, mbase + m2, lane);

#pragma unroll 2
            for (int j = 0; j < K8X; j++) {
                const int slot = j & 1;
                uint32_t bfr[4][2];
                ldB(Wf, j, lane, bfr);
#pragma unroll
                for (int m2 = 0; m2 < 2; m2++)
#pragma unroll
                    for (int nt = 0; nt < 4; nt++)
                        mma_tf32(acc[m2][nt], (const uint32_t*)&apf[slot][m2], bfr[nt]);
                if (j + 2 < K8X) {
#pragma unroll
                    for (int m2 = 0; m2 < 2; m2++)
                        apf[slot][m2] = ldX(t, j + 2, mbase + m2, lane);
                }
            }

            // write gx[t][blk][row][col]: float2 per (m2,nt,ch)
            float* gxt = &d_gx[((size_t)t * NBLK + blk) * (BATCH * 32)];
#pragma unroll
            for (int m2 = 0; m2 < 2; m2++)
#pragma unroll
                for (int nt = 0; nt < 4; nt++)
#pragma unroll
                    for (int ch = 0; ch < 2; ch++) {
                        int row = (mbase + m2) * 16 + g8 + 8 * ch;
                        int col = nt * 8 + 2 * ql;
                        __stcg((float2*)&gxt[row * 32 + col],
                               make_float2(acc[m2][nt][2 * ch], acc[m2][nt][2 * ch + 1]));
                    }
        }
    }
    __threadfence();
    __syncthreads();   // gx (own CTA) visible to all threads of this CTA

    // ================= RECURRENT LOOP (K = 1024, h only) ====================
    const int kslice = wid >> 1;          // 0..7
    const int mhalf  = wid & 1;
    const int h8base = kslice * HSL;      // k8 within h region (0..127)
    const int mbase  = mhalf * 2;

    const int bp = tid >> 3, up = tid & 7;
    float cst = 0.f;
    float bias[4];
#pragma unroll
    for (int g = 0; g < 4; g++)
        bias[g] = __ldg(&d_bias[blk * 32 + g * 8 + up]);

    for (int t = 0; t < SEQT; t++) {
        const int rbuf = t & 1, wbuf = rbuf ^ 1;

        // prefetch own-CTA gx for this step (no dependency -> before the wait)
        float gxv[4];
        {
            const float* gxt = &d_gx[((size_t)t * NBLK + blk) * (BATCH * 32)];
#pragma unroll
            for (int g = 0; g < 4; g++)
                gxv[g] = __ldcg(&gxt[bp * 32 + g * 8 + up]);
        }

        // -------- wait for peers' h(t-1) --------
        if (t > 0) {
            if (tid == 0) {
                while (*(volatile unsigned*)&d_bar_root < 8u * (unsigned)t)
                    __nanosleep(32);
                __threadfence();
            }
            __syncthreads();
        }

        // -------- h-MMA phase: M=32 x N=32, K=128 per warp, no syncs -------
        float acc[2][4][4];
#pragma unroll
        for (int m2 = 0; m2 < 2; m2++)
#pragma unroll
            for (int nt = 0; nt < 4; nt++)
#pragma unroll
                for (int c = 0; c < 4; c++) acc[m2][nt][c] = 0.f;

        uint4 apf[3][2];
#pragma unroll
        for (int d = 0; d < 3; d++)
#pragma unroll
            for (int m2 = 0; m2 < 2; m2++)
                apf[d][m2] = ldH(rbuf, h8base + d, mbase + m2, lane);

#pragma unroll 4
        for (int j = 0; j < HSL; j++) {
            const int slot = j % 3;
            uint32_t bfr[4][2];
            ldB(Wf, K8X + h8base + j, lane, bfr);
#pragma unroll
            for (int m2 = 0; m2 < 2; m2++)
#pragma unroll
                for (int nt = 0; nt < 4; nt++)
                    mma_tf32(acc[m2][nt], (const uint32_t*)&apf[slot][m2], bfr[nt]);
            if (j + 3 < HSL) {
#pragma unroll
                for (int m2 = 0; m2 < 2; m2++)
                    apf[slot][m2] = ldH(rbuf, h8base + j + 3, mbase + m2, lane);
            }
        }

        // -------- two-phase partial merge into 8 tiles --------
        float* Pw = P + (wid & 7) * P_TILE;
        if (wid < 8) {
#pragma unroll
            for (int m2 = 0; m2 < 2; m2++)
#pragma unroll
                for (int nt = 0; nt < 4; nt++)
#pragma unroll
                    for (int c = 0; c < 4; c++) {
                        int row = m2 * 16 + g8 + 8 * (c >> 1);
                        int col = nt * 8 + 2 * ql + (c & 1);
                        Pw[row * P_PITCH + col] = acc[m2][nt][c];
                    }
        }
        __syncthreads();
        if (wid >= 8) {
#pragma unroll
            for (int m2 = 0; m2 < 2; m2++)
#pragma unroll
                for (int nt = 0; nt < 4; nt++)
#pragma unroll
                    for (int c = 0; c < 4; c++) {
                        int row = m2 * 16 + g8 + 8 * (c >> 1);
                        int col = nt * 8 + 2 * ql + (c & 1);
                        Pw[row * P_PITCH + col] += acc[m2][nt][c];
                    }
        }
        __syncthreads();

        // -------- reduction + gate fusion (1 pair per thread) --------
        {
            const int mh = bp >> 5, r = bp & 31;
            float pa[4];
#pragma unroll
            for (int g = 0; g < 4; g++) {
                float s = bias[g] + gxv[g];
#pragma unroll
                for (int ks = 0; ks < 4; ks++)
                    s += P[(ks * 2 + mh) * P_TILE + r * P_PITCH + g * 8 + up];
                pa[g] = s;
            }
            float f = sigf(pa[0]), ig = sigf(pa[1]);
            float ch = tanhfast(pa[2]), o = sigf(pa[3]);
            cst = f * cst + ig * ch;
            float hv = tf32r(o * tanhfast(cst));
            int ug = blk * 8 + up;
            if (t < SEQT - 1) {
                int hidx = ug >> 3;
                int mtw  = bp >> 4;
                int lw   = (bp & 7) * 4 + (ug & 3);
                int rw   = 2 * ((ug >> 2) & 1) + ((bp >> 3) & 1);
                __stcg(&d_hfrag[(((size_t)(wbuf * 128 + hidx) * 4 + mtw) * 32 + lw) * 4 + rw], hv);
            } else {
                d_hfin[bp * HID + ug] = hv;
            }
        }

        // -------- arrive (release h(t)) --------
        __syncthreads();
        if (tid == 0) {
            __threadfence();
            const unsigned grp = (unsigned)(blk >> 4);
            unsigned v = atomicAdd(&d_bar_grp[grp * 64], 1u) + 1u;
            if (v == 16u * (unsigned)(t + 1))
                atomicAdd(&d_bar_root, 1u);
        }
    }

    // final wait: all CTAs' last h written before the tail GEMM
    if (tid == 0) {
        while (*(volatile unsigned*)&d_bar_root < 8u * (unsigned)SEQT)
            __nanosleep(32);
        __threadfence();
    }
    __syncthreads();

    // ---- tail: out[b][o] = h_final[b] . Wout[o] + bout[o]
    if (tid < 256) {
        const int gtid = blk * 256 + tid;
        const int b = gtid & 63, o = gtid >> 6;
        const float4* hr = (const float4*)&d_hfin[(size_t)b * HID];
        const float4* wr = (const float4*)(Wout + ((size_t)o << 10));
        float s = __ldg(&bout[o]);
#pragma unroll 4
        for (int k = 0; k < HID / 4; k++) {
            float4 h4 = __ldcg(hr + k);
            float4 w4 = __ldg(wr + k);
            s += h4.x * w4.x + h4.y * w4.y + h4.z * w4.z + h4.w * w4.w;
        }
        out[(size_t)b * OUTD + o] = s;
    }
}

// ============================================================================
extern "C" void kernel_launch(void* const* d_in, const int* in_sizes, int n_in,
                              void* d_out, int out_size)
{
    (void)in_sizes; (void)n_in; (void)out_size;
    const float* x    = (const float*)d_in[0];
    const float* Wxf  = (const float*)d_in[1];
    const float* Whf  = (const float*)d_in[2];
    const float* bhf  = (const float*)d_in[3];
    const float* Wxi  = (const float*)d_in[4];
    const float* Whi  = (const float*)d_in[5];
    const float* bhi  = (const float*)d_in[6];
    const float* Wxc  = (const float*)d_in[7];
    const float* Whc  = (const float*)d_in[8];
    const float* bhc  = (const float*)d_in[9];
    const float* Wxo  = (const float*)d_in[10];
    const float* Who  = (const float*)d_in[11];
    const float* bho  = (const float*)d_in[12];
    const float* Wout = (const float*)d_in[13];
    const float* bout = (const float*)d_in[14];
    float* out = (float*)d_out;

    cudaFuncSetAttribute(lstm_kernel,
                         cudaFuncAttributeMaxDynamicSharedMemorySize, SMEM_TOTAL);

    prep_kernel<<<2048, 256>>>(x, Wxf, Whf, bhf, Wxi, Whi, bhi,
                               Wxc, Whc, bhc, Wxo, Who, bho);
    lstm_kernel<<<NBLK, NTHR, SMEM_TOTAL>>>(Wout, bout, out);
}

// round 12
// speedup vs baseline: 1.4784x; 1.4784x over previous
#include <cuda_runtime.h>
#include <cstdint>

// Problem constants
#define BATCH 64
#define SEQT  512
#define IN    512
#define HID   1024
#define G4    4096
#define KTOT  1536
#define OUTD  512

#define NBLK  128           // persistent grid, 1 CTA/SM
#define NTHR  512           // 16 warps = (kslice 0..7) x (mhalf 0..1)
#define K8TOT 192           // total k8 (x: 0..63, h: 64..191)
#define K8X   64
#define KSL   24            // k8 per warp K-slice (192/8)

// smem: W fragment-packed (resident, LDS.128 layout) + 8 merged partial tiles
#define WF_FLOATS (K8TOT * 32 * 8)         // 49152 floats = 196608 B
#define P_PITCH   33
#define P_TILE    (32 * P_PITCH)
#define SMEM_TOTAL ((WF_FLOATS + 8 * P_TILE) * 4)   // 230400 B

// ---- device-global scratch ----
__device__ float    d_W[(size_t)G4 * KTOT];              // tf32-rounded, packed cols
__device__ float    d_bias[G4];
__device__ float    d_xfrag[(size_t)SEQT * K8X * 4 * 32 * 4]; // x in fragment order
__device__ float    d_hfrag[2 * 128 * 4 * 32 * 4];       // h fragments, dbl-buf
__device__ float    d_hfin[BATCH * HID];
__device__ unsigned d_bar_grp[8 * 64];                   // spread group counters
__device__ unsigned d_bar_root;

// ============================ helpers =======================================
__device__ __forceinline__ float tf32r(float v) {
    uint32_t r;
    asm("cvt.rna.tf32.f32 %0, %1;" : "=r"(r) : "f"(v));
    return __uint_as_float(r);
}
__device__ __forceinline__ void mma_tf32(float c[4], const uint32_t a[4],
                                         const uint32_t b[2]) {
    asm volatile(
        "mma.sync.aligned.m16n8k8.row.col.f32.tf32.tf32.f32 "
        "{%0,%1,%2,%3}, {%4,%5,%6,%7}, {%8,%9}, {%0,%1,%2,%3};"
        : "+f"(c[0]), "+f"(c[1]), "+f"(c[2]), "+f"(c[3])
        : "r"(a[0]), "r"(a[1]), "r"(a[2]), "r"(a[3]), "r"(b[0]), "r"(b[1]));
}
__device__ __forceinline__ float sigf(float v)     { return 1.f / (1.f + __expf(-v)); }
__device__ __forceinline__ float tanhfast(float v) { return 2.f / (1.f + __expf(-2.f * v)) - 1.f; }

// ============================ prep kernel ===================================
// Packed W column j: gate g=(j>>3)&3 (f,i,c,o), unit=(j>>5)*8+(j&7).
// x fragments: [t][k8][mt][lane][reg]; b = mt*16+(lane>>2)+8*(reg&1),
//              k = k8*8+(lane&3)+4*(reg>>1)
__global__ void prep_kernel(
    const float* __restrict__ x,
    const float* __restrict__ Wxf, const float* __restrict__ Whf, const float* __restrict__ bhf,
    const float* __restrict__ Wxi, const float* __restrict__ Whi, const float* __restrict__ bhi,
    const float* __restrict__ Wxc, const float* __restrict__ Whc, const float* __restrict__ bhc,
    const float* __restrict__ Wxo, const float* __restrict__ Who, const float* __restrict__ bho)
{
    const float* Wx[4] = {Wxf, Wxi, Wxc, Wxo};
    const float* Wh[4] = {Whf, Whi, Whc, Who};
    const float* bh[4] = {bhf, bhi, bhc, bho};

    size_t gid = (size_t)blockIdx.x * blockDim.x + threadIdx.x;
    size_t str = (size_t)gridDim.x * blockDim.x;

    for (size_t i = gid; i < (size_t)G4 * KTOT; i += str) {
        int j = (int)(i / KTOT), k = (int)(i % KTOT);
        int g = (j >> 3) & 3;
        int r = (j >> 5) * 8 + (j & 7);
        float v = (k < IN) ? Wx[g][(size_t)r * IN + k]
                           : Wh[g][(size_t)r * HID + (k - IN)];
        d_W[i] = tf32r(v);
    }
    for (size_t i = gid; i < (size_t)G4; i += str) {
        int g = (int)((i >> 3) & 3);
        int r = (int)((i >> 5) * 8 + (i & 7));
        d_bias[i] = bh[g][r];
    }
    for (size_t i = gid; i < (size_t)SEQT * K8X * 4 * 32 * 4; i += str) {
        int r    = (int)(i & 3);
        int lane = (int)((i >> 2) & 31);
        int mt   = (int)((i >> 7) & 3);
        int k8   = (int)((i >> 9) & 63);
        int t    = (int)(i >> 15);
        int b = mt * 16 + (lane >> 2) + 8 * (r & 1);
        int k = k8 * 8 + (lane & 3) + 4 * (r >> 1);
        d_xfrag[i] = tf32r(x[((size_t)b * SEQT + t) * IN + k]);
    }
    for (size_t i = gid; i < (size_t)2 * 128 * 4 * 32 * 4; i += str)
        d_hfrag[i] = 0.f;
    for (size_t i = gid; i < 8 * 64; i += str) d_bar_grp[i] = 0u;
    if (gid == 0) d_bar_root = 0u;
}

// ============================ fragment loads ================================
// A-fragment load: one LDG.128, coalesced across the warp
__device__ __forceinline__ uint4 ldA(int t, int rbuf, int k8, int mt, int lane)
{
    if (k8 < K8X) {
        size_t off = ((((size_t)t * K8X + k8) * 4 + mt) * 32 + lane) * 4;
        return __ldg((const uint4*)&d_xfrag[off]);
    } else {
        size_t off = (((size_t)(rbuf * 128 + (k8 - K8X)) * 4 + mt) * 32 + lane) * 4;
        return __ldcg((const uint4*)&d_hfrag[off]);
    }
}
// B fragments for one k8: 2 x LDS.128 from fragment-packed Wf
__device__ __forceinline__ void ldB(const float* Wf, int k8, int lane, uint32_t bfr[4][2])
{
    const float4* p = (const float4*)&Wf[(size_t)(k8 * 32 + lane) * 8];
    float4 w0 = p[0], w1 = p[1];
    bfr[0][0] = __float_as_uint(w0.x); bfr[0][1] = __float_as_uint(w0.y);
    bfr[1][0] = __float_as_uint(w0.z); bfr[1][1] = __float_as_uint(w0.w);
    bfr[2][0] = __float_as_uint(w1.x); bfr[2][1] = __float_as_uint(w1.y);
    bfr[3][0] = __float_as_uint(w1.z); bfr[3][1] = __float_as_uint(w1.w);
}

// per-warp wait on the barrier root
__device__ __forceinline__ void warp_wait_root(unsigned target, int lane)
{
    if (lane == 0) {
        while (*(volatile unsigned*)&d_bar_root < target) __nanosleep(32);
        __threadfence();
    }
    __syncwarp();
}

// ============================ main persistent kernel ========================
__global__ void __launch_bounds__(NTHR, 1) lstm_kernel(
    const float* __restrict__ Wout,
    const float* __restrict__ bout,
    float* __restrict__ out)
{
    extern __shared__ float smf[];
    float* Wf = smf;                 // fragment-packed weights
    float* P  = smf + WF_FLOATS;     // 8 merged partial tiles

    const int tid  = threadIdx.x;
    const int wid  = tid >> 5;
    const int lane = tid & 31;
    const int g8   = lane >> 2;
    const int ql   = lane & 3;
    const int blk  = blockIdx.x;

    const int kslice = wid >> 1;          // 0..7
    const int mhalf  = wid & 1;           // batch half
    const int k8base = kslice * KSL;
    const int mbase  = mhalf * 2;         // mt in {mbase, mbase+1}
    const bool needs_h = (k8base + KSL > K8X);   // kslices 2..7 touch h
    const bool pre_ok  = (k8base + 2 < K8X);     // first 3 prefetch k8s are x

    // ---- one-time: pack W columns into LDS.128-friendly fragment order ----
    // Wf[(k8*32+lane)*8 + nt*2 + s] = W[blk*32+nt*8+(lane>>2)][k8*8+(lane&3)+4s]
    for (int j = tid; j < K8TOT * 32; j += NTHR) {
        int k8 = j >> 5, ln = j & 31;
        int g8l = ln >> 2, qll = ln & 3;
#pragma unroll
        for (int nt = 0; nt < 4; nt++) {
            size_t col = (size_t)(blk * 32 + nt * 8 + g8l);
            Wf[(size_t)j * 8 + nt * 2 + 0] = __ldg(&d_W[col * KTOT + k8 * 8 + qll]);
            Wf[(size_t)j * 8 + nt * 2 + 1] = __ldg(&d_W[col * KTOT + k8 * 8 + qll + 4]);
        }
    }
    __syncthreads();

    // ---- epilogue persistent state: each thread owns ONE (b,u) pair ----
    const int bp = tid >> 3, up = tid & 7;
    float cst = 0.f;
    float bias[4];
#pragma unroll
    for (int g = 0; g < 4; g++)
        bias[g] = __ldg(&d_bias[blk * 32 + g * 8 + up]);

    for (int t = 0; t < SEQT; t++) {
        const int rbuf = t & 1, wbuf = rbuf ^ 1;

        // -------- per-warp wait for peers' h(t-1); x-only warps skip -------
        float acc[2][4][4];
#pragma unroll
        for (int m2 = 0; m2 < 2; m2++)
#pragma unroll
            for (int nt = 0; nt < 4; nt++)
#pragma unroll
                for (int c = 0; c < 4; c++) acc[m2][nt][c] = 0.f;

        uint4 apf[3][2];
        if (pre_ok) {       // x-region prefetch is barrier-independent
#pragma unroll
            for (int d = 0; d < 3; d++)
#pragma unroll
                for (int m2 = 0; m2 < 2; m2++)
                    apf[d][m2] = ldA(t, rbuf, k8base + d, mbase + m2, lane);
        }
        if (needs_h && t > 0)
            warp_wait_root(8u * (unsigned)t, lane);
        if (!pre_ok) {
#pragma unroll
            for (int d = 0; d < 3; d++)
#pragma unroll
                for (int m2 = 0; m2 < 2; m2++)
                    apf[d][m2] = ldA(t, rbuf, k8base + d, mbase + m2, lane);
        }

        // -------- MMA phase: M=32 x N=32, K=192 per warp, no syncs ---------
#pragma unroll 3
        for (int j = 0; j < KSL; j++) {
            const int slot = j % 3;
            uint32_t bfr[4][2];
            ldB(Wf, k8base + j, lane, bfr);
#pragma unroll
            for (int m2 = 0; m2 < 2; m2++)
#pragma unroll
                for (int nt = 0; nt < 4; nt++)
                    mma_tf32(acc[m2][nt], (const uint32_t*)&apf[slot][m2], bfr[nt]);
            if (j + 3 < KSL) {
#pragma unroll
                for (int m2 = 0; m2 < 2; m2++)
                    apf[slot][m2] = ldA(t, rbuf, k8base + j + 3, mbase + m2, lane);
            }
        }

        // -------- two-phase partial merge into 8 tiles --------
        float* Pw = P + (wid & 7) * P_TILE;
        if (wid < 8) {
#pragma unroll
            for (int m2 = 0; m2 < 2; m2++)
#pragma unroll
                for (int nt = 0; nt < 4; nt++)
#pragma unroll
                    for (int c = 0; c < 4; c++) {
                        int row = m2 * 16 + g8 + 8 * (c >> 1);
                        int col = nt * 8 + 2 * ql + (c & 1);
                        Pw[row * P_PITCH + col] = acc[m2][nt][c];
                    }
        }
        __syncthreads();
        if (wid >= 8) {
#pragma unroll
            for (int m2 = 0; m2 < 2; m2++)
#pragma unroll
                for (int nt = 0; nt < 4; nt++)
#pragma unroll
                    for (int c = 0; c < 4; c++) {
                        int row = m2 * 16 + g8 + 8 * (c >> 1);
                        int col = nt * 8 + 2 * ql + (c & 1);
                        Pw[row * P_PITCH + col] += acc[m2][nt][c];
                    }
        }
        __syncthreads();

        // -------- reduction + gate fusion (1 pair per thread) --------
        {
            const int mh = bp >> 5, r = bp & 31;
            float pa[4];
#pragma unroll
            for (int g = 0; g < 4; g++) {
                float s = bias[g];
#pragma unroll
                for (int ks = 0; ks < 4; ks++)
                    s += P[(ks * 2 + mh) * P_TILE + r * P_PITCH + g * 8 + up];
                pa[g] = s;
            }
            float f = sigf(pa[0]), ig = sigf(pa[1]);
            float ch = tanhfast(pa[2]), o = sigf(pa[3]);
            cst = f * cst + ig * ch;
            float hv = tf32r(o * tanhfast(cst));
            int ug = blk * 8 + up;
            if (t < SEQT - 1) {
                int hidx = ug >> 3;
                int mtw  = bp >> 4;
                int lw   = (bp & 7) * 4 + (ug & 3);
                int rw   = 2 * ((ug >> 2) & 1) + ((bp >> 3) & 1);
                __stcg(&d_hfrag[(((size_t)(wbuf * 128 + hidx) * 4 + mtw) * 32 + lw) * 4 + rw], hv);
            } else {
                d_hfin[bp * HID + ug] = hv;
            }
        }

        // -------- arrive (release h(t)) --------
        __syncthreads();
        if (tid == 0) {
            __threadfence();
            const unsigned grp = (unsigned)(blk >> 4);
            unsigned v = atomicAdd(&d_bar_grp[grp * 64], 1u) + 1u;
            if (v == 16u * (unsigned)(t + 1))
                atomicAdd(&d_bar_root, 1u);
        }
    }

    // final wait: all CTAs' last h written before the tail GEMM
    warp_wait_root(8u * (unsigned)SEQT, lane);
    __syncthreads();

    // ---- tail: out[b][o] = h_final[b] . Wout[o] + bout[o]
    if (tid < 256) {
        const int gtid = blk * 256 + tid;
        const int b = gtid & 63, o = gtid >> 6;
        const float4* hr = (const float4*)&d_hfin[(size_t)b * HID];
        const float4* wr = (const float4*)(Wout + ((size_t)o << 10));
        float s = __ldg(&bout[o]);
#pragma unroll 4
        for (int k = 0; k < HID / 4; k++) {
            float4 h4 = __ldcg(hr + k);
            float4 w4 = __ldg(wr + k);
            s += h4.x * w4.x + h4.y * w4.y + h4.z * w4.z + h4.w * w4.w;
        }
        out[(size_t)b * OUTD + o] = s;
    }
}

// ============================================================================
extern "C" void kernel_launch(void* const* d_in, const int* in_sizes, int n_in,
                              void* d_out, int out_size)
{
    (void)in_sizes; (void)n_in; (void)out_size;
    const float* x    = (const float*)d_in[0];
    const float* Wxf  = (const float*)d_in[1];
    const float* Whf  = (const float*)d_in[2];
    const float* bhf  = (const float*)d_in[3];
    const float* Wxi  = (const float*)d_in[4];
    const float* Whi  = (const float*)d_in[5];
    const float* bhi  = (const float*)d_in[6];
    const float* Wxc  = (const float*)d_in[7];
    const float* Whc  = (const float*)d_in[8];
    const float* bhc  = (const float*)d_in[9];
    const float* Wxo  = (const float*)d_in[10];
    const float* Who  = (const float*)d_in[11];
    const float* bho  = (const float*)d_in[12];
    const float* Wout = (const float*)d_in[13];
    const float* bout = (const float*)d_in[14];
    float* out = (float*)d_out;

    cudaFuncSetAttribute(lstm_kernel,
                         cudaFuncAttributeMaxDynamicSharedMemorySize, SMEM_TOTAL);

    prep_kernel<<<2048, 256>>>(x, Wxf, Whf, bhf, Wxi, Whi, bhi,
                               Wxc, Whc, bhc, Wxo, Who, bho);
    lstm_kernel<<<NBLK, NTHR, SMEM_TOTAL>>>(Wout, bout, out);
}